// round 2
// baseline (speedup 1.0000x reference)
#include <cuda_runtime.h>
#include <math.h>

#define TT 1024
#define BB 4
#define HH 1024
#define VV 32000
#define NBLK 128
#define UPB 8   // hidden units per block in recurrence (128*8 = 1024)

// ---------------- scratch (static device globals; no allocation) ----------------
__device__ float g_feats[(size_t)TT * BB * HH];        // embedded input, time-major [T][B][H]
__device__ float g_gates[(size_t)TT * BB * 4 * HH];    // precomputed input-side gates [T][B][4H]
__device__ float g_h0[(size_t)TT * BB * HH];           // layer0 outputs [T][B][H]
__device__ float g_h1[(size_t)TT * BB * HH];           // layer1 outputs [T][B][H]
__device__ float g_xn[(size_t)TT * BB * HH];           // layernorm output, batch-major [B][T][H]
__device__ int   g_flags[NBLK];

// ---------------- embedding: feats[t][b][:] = word_emb[ids[b][t]] + pos_emb[t] ----------------
__global__ void embed_kernel(const int* __restrict__ ids, const float* __restrict__ we,
                             const float* __restrict__ pe, float* __restrict__ out)
{
    int t = blockIdx.x, b = blockIdx.y;
    int id = ids[b * TT + t];
    const float4* w = (const float4*)(we + (size_t)id * HH);
    const float4* p = (const float4*)(pe + (size_t)t * HH);
    float4* o = (float4*)(out + ((size_t)t * BB + b) * HH);
    for (int i = threadIdx.x; i < HH / 4; i += blockDim.x) {
        float4 a = w[i], c = p[i];
        o[i] = make_float4(a.x + c.x, a.y + c.y, a.z + c.z, a.w + c.w);
    }
}

// ---------------- generic NT GEMM: C[m][n] = sum_k A[m][k]*B[n][k] (+ bias0[n]+bias1[n]) --------
// BM=BN=128, BK=16, 256 threads, 8x8 register tile. All dims divisible by tile sizes.
__global__ __launch_bounds__(256) void gemm_nt_kernel(
    const float* __restrict__ A, const float* __restrict__ B,
    const float* __restrict__ bias0, const float* __restrict__ bias1,
    float* __restrict__ C, int M, int N, int K)
{
    __shared__ float As[16][132];
    __shared__ float Bs[16][132];
    const int bn = blockIdx.x << 7;
    const int bm = blockIdx.y << 7;
    const int tid = threadIdx.x;
    const int tm = (tid >> 4) << 3;   // output row offset within tile
    const int tn = (tid & 15) << 3;   // output col offset within tile

    float acc[8][8];
#pragma unroll
    for (int i = 0; i < 8; ++i)
#pragma unroll
        for (int j = 0; j < 8; ++j) acc[i][j] = 0.f;

    for (int kk = 0; kk < K; kk += 16) {
#pragma unroll
        for (int i = 0; i < 2; ++i) {
            int l = tid + (i << 8);          // 0..511
            int row = l >> 2;                // 0..127
            int kq = (l & 3) << 2;           // 0,4,8,12
            float4 av = *(const float4*)(A + (size_t)(bm + row) * K + kk + kq);
            As[kq + 0][row] = av.x; As[kq + 1][row] = av.y;
            As[kq + 2][row] = av.z; As[kq + 3][row] = av.w;
            float4 bv = *(const float4*)(B + (size_t)(bn + row) * K + kk + kq);
            Bs[kq + 0][row] = bv.x; Bs[kq + 1][row] = bv.y;
            Bs[kq + 2][row] = bv.z; Bs[kq + 3][row] = bv.w;
        }
        __syncthreads();
#pragma unroll
        for (int k = 0; k < 16; ++k) {
            float ar[8], br[8];
            *(float4*)(ar)     = *(const float4*)(&As[k][tm]);
            *(float4*)(ar + 4) = *(const float4*)(&As[k][tm + 4]);
            *(float4*)(br)     = *(const float4*)(&Bs[k][tn]);
            *(float4*)(br + 4) = *(const float4*)(&Bs[k][tn + 4]);
#pragma unroll
            for (int i = 0; i < 8; ++i)
#pragma unroll
                for (int j = 0; j < 8; ++j)
                    acc[i][j] = fmaf(ar[i], br[j], acc[i][j]);
        }
        __syncthreads();
    }

    float bias[8];
#pragma unroll
    for (int j = 0; j < 8; ++j) bias[j] = 0.f;
    if (bias0) {
#pragma unroll
        for (int j = 0; j < 8; ++j) bias[j] = bias0[bn + tn + j] + bias1[bn + tn + j];
    }
#pragma unroll
    for (int i = 0; i < 8; ++i) {
        float* cp = C + (size_t)(bm + tm + i) * N + bn + tn;
        float4 v0 = make_float4(acc[i][0] + bias[0], acc[i][1] + bias[1],
                                acc[i][2] + bias[2], acc[i][3] + bias[3]);
        float4 v1 = make_float4(acc[i][4] + bias[4], acc[i][5] + bias[5],
                                acc[i][6] + bias[6], acc[i][7] + bias[7]);
        *(float4*)cp = v0;
        *(float4*)(cp + 4) = v1;
    }
}

// ---------------- persistent LSTM recurrence (one layer) ----------------
// 128 blocks, each owns 8 hidden units. W_hh shard (32 rows x 1024) lives in SMEM
// for all 1024 timesteps. Per-step software grid barrier via g_flags.
__device__ __forceinline__ float sigm(float x) { return 1.f / (1.f + expf(-x)); }

__global__ __launch_bounds__(256) void lstm_layer_kernel(
    const float* __restrict__ gates_in,   // [T][B][4H] (includes biases)
    const float* __restrict__ Whh,        // [4H][H]
    float* __restrict__ hout,             // [T][B][H]
    int* flags)
{
    extern __shared__ float sm[];
    float* Wsh  = sm;                       // [32][1028] padded rows
    float* hsh  = Wsh + 32 * 1028;          // [4][1024] h_prev
    float* part = hsh + 4 * 1024;           // [8][32][4] partial dots
    float* gsm  = part + 8 * 32 * 4;        // [32][4] gate sums
    float* csh  = gsm + 32 * 4;             // [32] cell state (u*4+b)

    const int tid = threadIdx.x;
    const int blk = blockIdx.x;
    const int u0 = blk * UPB;

    // load weight shard: row r = g*8+u  ->  Whh[g*H + u0+u][:]
#pragma unroll
    for (int r = 0; r < 32; ++r) {
        int g = r >> 3, u = r & 7;
        const float* src = Whh + (size_t)(g * HH + u0 + u) * HH;
        *(float4*)(Wsh + r * 1028 + tid * 4) = *(const float4*)(src + tid * 4);
    }
    if (tid < 32) csh[tid] = 0.f;
    for (int i = tid * 4; i < BB * HH; i += 1024)
        *(float4*)(hsh + i) = make_float4(0.f, 0.f, 0.f, 0.f);
    __syncthreads();

    const int j  = tid & 31;   // gate-unit index: g = j>>3, u = j&7
    const int ks = tid >> 5;   // k-slice 0..7 (warp id)

    for (int t = 0; t < TT; ++t) {
        if (t > 0) {
            if (tid < NBLK) {
                volatile int* f = flags + tid;
                while (*f < t) { }
            }
            __syncthreads();
            __threadfence();
            const float* hp = hout + (size_t)(t - 1) * BB * HH;
            for (int i = tid * 4; i < BB * HH; i += 1024)
                *(float4*)(hsh + i) = __ldcg((const float4*)(hp + i));
            __syncthreads();
        }

        // partial dot products: acc[b] = sum_{k in slice} Wsh[j][k] * h[b][k]
        {
            const float* wr = Wsh + j * 1028 + (ks << 7);
            const float* hb = hsh + (ks << 7);
            float a0 = 0.f, a1 = 0.f, a2 = 0.f, a3 = 0.f;
#pragma unroll 8
            for (int k = 0; k < 128; k += 4) {
                float4 wv = *(const float4*)(wr + k);
                float4 x0 = *(const float4*)(hb + k);
                float4 x1 = *(const float4*)(hb + 1024 + k);
                float4 x2 = *(const float4*)(hb + 2048 + k);
                float4 x3 = *(const float4*)(hb + 3072 + k);
                a0 = fmaf(wv.x, x0.x, a0); a0 = fmaf(wv.y, x0.y, a0);
                a0 = fmaf(wv.z, x0.z, a0); a0 = fmaf(wv.w, x0.w, a0);
                a1 = fmaf(wv.x, x1.x, a1); a1 = fmaf(wv.y, x1.y, a1);
                a1 = fmaf(wv.z, x1.z, a1); a1 = fmaf(wv.w, x1.w, a1);
                a2 = fmaf(wv.x, x2.x, a2); a2 = fmaf(wv.y, x2.y, a2);
                a2 = fmaf(wv.z, x2.z, a2); a2 = fmaf(wv.w, x2.w, a2);
                a3 = fmaf(wv.x, x3.x, a3); a3 = fmaf(wv.y, x3.y, a3);
                a3 = fmaf(wv.z, x3.z, a3); a3 = fmaf(wv.w, x3.w, a3);
            }
            *(float4*)(part + ((ks << 5) + j) * 4) = make_float4(a0, a1, a2, a3);
        }
        __syncthreads();

        // reduce across k-slices, add precomputed input gates
        if (tid < 128) {
            int jj = tid >> 2, b = tid & 3;
            float s = 0.f;
#pragma unroll
            for (int q = 0; q < 8; ++q) s += part[((q << 5) + jj) * 4 + b];
            int g = jj >> 3, u = jj & 7;
            s += gates_in[((size_t)t * BB + b) * (4 * HH) + g * HH + u0 + u];
            gsm[jj * 4 + b] = s;
        }
        __syncthreads();

        // LSTM cell for this block's (u,b)
        if (tid < 32) {
            int u = tid >> 2, b = tid & 3;
            float gi = gsm[(0 * 8 + u) * 4 + b];
            float gf = gsm[(1 * 8 + u) * 4 + b];
            float gc = gsm[(2 * 8 + u) * 4 + b];
            float go = gsm[(3 * 8 + u) * 4 + b];
            float c  = csh[tid];
            float cn = sigm(gf) * c + sigm(gi) * tanhf(gc);
            float hn = sigm(go) * tanhf(cn);
            csh[tid] = cn;
            hout[((size_t)t * BB + b) * HH + u0 + u] = hn;
            __threadfence();
        }
        __syncthreads();
        if (tid == 0) {
            __threadfence();
            ((volatile int*)flags)[blk] = t + 1;
        }
    }
}

__global__ void reset_flags_kernel(int* f)
{
    if (threadIdx.x < NBLK) f[threadIdx.x] = 0;
}

// ---------------- LayerNorm + layout change to batch-major ----------------
__global__ __launch_bounds__(256) void layernorm_kernel(
    const float* __restrict__ in,   // [T][B][H]
    const float* __restrict__ w, const float* __restrict__ bv,
    float* __restrict__ out)        // [B][T][H]
{
    int t = blockIdx.x, b = blockIdx.y;
    const float* x = in + ((size_t)t * BB + b) * HH;
    float* o = out + ((size_t)b * TT + t) * HH;
    __shared__ float row[HH];
    __shared__ float red[8];
    __shared__ float stat[2];
    int tid = threadIdx.x;

    float s = 0.f;
    for (int i = tid; i < HH; i += 256) { float v = x[i]; row[i] = v; s += v; }
#pragma unroll
    for (int off = 16; off; off >>= 1) s += __shfl_xor_sync(0xffffffffu, s, off);
    if ((tid & 31) == 0) red[tid >> 5] = s;
    __syncthreads();
    if (tid == 0) {
        float tot = 0.f;
        for (int i = 0; i < 8; ++i) tot += red[i];
        stat[0] = tot * (1.f / HH);
    }
    __syncthreads();
    float mu = stat[0];

    float v2 = 0.f;
    for (int i = tid; i < HH; i += 256) { float d = row[i] - mu; v2 += d * d; }
#pragma unroll
    for (int off = 16; off; off >>= 1) v2 += __shfl_xor_sync(0xffffffffu, v2, off);
    __syncthreads();
    if ((tid & 31) == 0) red[tid >> 5] = v2;
    __syncthreads();
    if (tid == 0) {
        float tot = 0.f;
        for (int i = 0; i < 8; ++i) tot += red[i];
        stat[1] = rsqrtf(tot * (1.f / HH) + 1e-5f);
    }
    __syncthreads();
    float inv = stat[1];
    for (int i = tid; i < HH; i += 256)
        o[i] = (row[i] - mu) * inv * w[i] + bv[i];
}

// ---------------- launch ----------------
extern "C" void kernel_launch(void* const* d_in, const int* in_sizes, int n_in,
                              void* d_out, int out_size)
{
    (void)in_sizes; (void)n_in; (void)out_size;
    const int*   ids = (const int*)d_in[0];
    const float* we  = (const float*)d_in[1];
    const float* pe  = (const float*)d_in[2];
    const float* Wih = (const float*)d_in[3];
    const float* Whh = (const float*)d_in[4];
    const float* bih = (const float*)d_in[5];
    const float* bhh = (const float*)d_in[6];
    const float* lnw = (const float*)d_in[7];
    const float* lnb = (const float*)d_in[8];
    float* out = (float*)d_out;

    float *feats, *gates, *h0, *h1, *xn; int* flags;
    cudaGetSymbolAddress((void**)&feats, g_feats);
    cudaGetSymbolAddress((void**)&gates, g_gates);
    cudaGetSymbolAddress((void**)&h0,    g_h0);
    cudaGetSymbolAddress((void**)&h1,    g_h1);
    cudaGetSymbolAddress((void**)&xn,    g_xn);
    cudaGetSymbolAddress((void**)&flags, g_flags);

    size_t smem = (size_t)(32 * 1028 + 4 * 1024 + 8 * 32 * 4 + 32 * 4 + 32) * sizeof(float);
    cudaFuncSetAttribute(lstm_layer_kernel,
                         cudaFuncAttributeMaxDynamicSharedMemorySize, (int)smem);

    // 1) embedding (time-major)
    embed_kernel<<<dim3(TT, BB), 256>>>(ids, we, pe, feats);

    // 2) layer0 input gates: feats @ W_ih0^T + b
    gemm_nt_kernel<<<dim3(4 * HH / 128, TT * BB / 128), 256>>>(
        feats, Wih, bih, bhh, gates, TT * BB, 4 * HH, HH);

    // 3) layer0 recurrence
    reset_flags_kernel<<<1, NBLK>>>(flags);
    lstm_layer_kernel<<<NBLK, 256, smem>>>(gates, Whh, h0, flags);

    // 4) layer1 input gates: h0 @ W_ih1^T + b
    gemm_nt_kernel<<<dim3(4 * HH / 128, TT * BB / 128), 256>>>(
        h0, Wih + (size_t)4 * HH * HH, bih + 4 * HH, bhh + 4 * HH,
        gates, TT * BB, 4 * HH, HH);

    // 5) layer1 recurrence
    reset_flags_kernel<<<1, NBLK>>>(flags);
    lstm_layer_kernel<<<NBLK, 256, smem>>>(gates, Whh + (size_t)4 * HH * HH, h1, flags);

    // 6) layernorm (also converts to batch-major rows)
    layernorm_kernel<<<dim3(TT, BB), 256>>>(h1, lnw, lnb, xn);

    // 7) tied LM head: logits[b*T+t][v] = xn @ word_emb^T
    gemm_nt_kernel<<<dim3(VV / 128, TT * BB / 128), 256>>>(
        xn, we, nullptr, nullptr, out, TT * BB, VV, HH);
}

// round 3
// speedup vs baseline: 1.3821x; 1.3821x over previous
#include <cuda_runtime.h>
#include <math.h>

#define TT 1024
#define BB 4
#define HH 1024
#define VV 32000
#define NBLK 128
#define UPB 8   // hidden units per block in recurrence (128*8 = 1024)

// ---------------- scratch (static device globals; no allocation) ----------------
__device__ float g_feats[(size_t)TT * BB * HH];        // embedded input, time-major [T][B][H]
__device__ float g_gates[(size_t)TT * BB * 4 * HH];    // precomputed input-side gates [T][B][4H]
__device__ float g_h0[(size_t)TT * BB * HH];           // layer0 outputs [T][B][H]
__device__ float g_h1[(size_t)TT * BB * HH];           // layer1 outputs [T][B][H]
__device__ float g_xn[(size_t)TT * BB * HH];           // layernorm output, batch-major [B][T][H]
__device__ int   g_flags[NBLK];

// ---------------- embedding: feats[t][b][:] = word_emb[ids[b][t]] + pos_emb[t] ----------------
__global__ void embed_kernel(const int* __restrict__ ids, const float* __restrict__ we,
                             const float* __restrict__ pe, float* __restrict__ out)
{
    int t = blockIdx.x, b = blockIdx.y;
    int id = ids[b * TT + t];
    const float4* w = (const float4*)(we + (size_t)id * HH);
    const float4* p = (const float4*)(pe + (size_t)t * HH);
    float4* o = (float4*)(out + ((size_t)t * BB + b) * HH);
    for (int i = threadIdx.x; i < HH / 4; i += blockDim.x) {
        float4 a = w[i], c = p[i];
        o[i] = make_float4(a.x + c.x, a.y + c.y, a.z + c.z, a.w + c.w);
    }
}

// ---------------- generic NT GEMM: C[m][n] = sum_k A[m][k]*B[n][k] (+ bias0[n]+bias1[n]) --------
// BM=BN=128, BK=16, 256 threads, 8x8 register tile. All dims divisible by tile sizes.
__global__ __launch_bounds__(256) void gemm_nt_kernel(
    const float* __restrict__ A, const float* __restrict__ B,
    const float* __restrict__ bias0, const float* __restrict__ bias1,
    float* __restrict__ C, int M, int N, int K)
{
    __shared__ float As[16][132];
    __shared__ float Bs[16][132];
    const int bn = blockIdx.x << 7;
    const int bm = blockIdx.y << 7;
    const int tid = threadIdx.x;
    const int tm = (tid >> 4) << 3;   // output row offset within tile
    const int tn = (tid & 15) << 3;   // output col offset within tile

    float acc[8][8];
#pragma unroll
    for (int i = 0; i < 8; ++i)
#pragma unroll
        for (int j = 0; j < 8; ++j) acc[i][j] = 0.f;

    for (int kk = 0; kk < K; kk += 16) {
#pragma unroll
        for (int i = 0; i < 2; ++i) {
            int l = tid + (i << 8);          // 0..511
            int row = l >> 2;                // 0..127
            int kq = (l & 3) << 2;           // 0,4,8,12
            float4 av = *(const float4*)(A + (size_t)(bm + row) * K + kk + kq);
            As[kq + 0][row] = av.x; As[kq + 1][row] = av.y;
            As[kq + 2][row] = av.z; As[kq + 3][row] = av.w;
            float4 bv = *(const float4*)(B + (size_t)(bn + row) * K + kk + kq);
            Bs[kq + 0][row] = bv.x; Bs[kq + 1][row] = bv.y;
            Bs[kq + 2][row] = bv.z; Bs[kq + 3][row] = bv.w;
        }
        __syncthreads();
#pragma unroll
        for (int k = 0; k < 16; ++k) {
            float ar[8], br[8];
            *(float4*)(ar)     = *(const float4*)(&As[k][tm]);
            *(float4*)(ar + 4) = *(const float4*)(&As[k][tm + 4]);
            *(float4*)(br)     = *(const float4*)(&Bs[k][tn]);
            *(float4*)(br + 4) = *(const float4*)(&Bs[k][tn + 4]);
#pragma unroll
            for (int i = 0; i < 8; ++i)
#pragma unroll
                for (int j = 0; j < 8; ++j)
                    acc[i][j] = fmaf(ar[i], br[j], acc[i][j]);
        }
        __syncthreads();
    }

    float bias[8];
#pragma unroll
    for (int j = 0; j < 8; ++j) bias[j] = 0.f;
    if (bias0) {
#pragma unroll
        for (int j = 0; j < 8; ++j) bias[j] = bias0[bn + tn + j] + bias1[bn + tn + j];
    }
#pragma unroll
    for (int i = 0; i < 8; ++i) {
        float* cp = C + (size_t)(bm + tm + i) * N + bn + tn;
        float4 v0 = make_float4(acc[i][0] + bias[0], acc[i][1] + bias[1],
                                acc[i][2] + bias[2], acc[i][3] + bias[3]);
        float4 v1 = make_float4(acc[i][4] + bias[4], acc[i][5] + bias[5],
                                acc[i][6] + bias[6], acc[i][7] + bias[7]);
        *(float4*)cp = v0;
        *(float4*)(cp + 4) = v1;
    }
}

// ---------------- persistent LSTM recurrence (one layer) ----------------
// 128 blocks, each owns 8 hidden units. W_hh shard (32 rows x 1024) lives in SMEM
// for all 1024 timesteps. Per-step software grid barrier via g_flags.
__device__ __forceinline__ float sigm(float x) { return 1.f / (1.f + expf(-x)); }

__global__ __launch_bounds__(256) void lstm_layer_kernel(
    const float* __restrict__ gates_in,   // [T][B][4H] (includes biases)
    const float* __restrict__ Whh,        // [4H][H]
    float* __restrict__ hout,             // [T][B][H]
    int* flags)
{
    extern __shared__ float sm[];
    float* Wsh  = sm;                       // [32][1028] padded rows
    float* hsh  = Wsh + 32 * 1028;          // [4][1024] h_prev
    float* part = hsh + 4 * 1024;           // [8][32][4] partial dots
    float* gsm  = part + 8 * 32 * 4;        // [32][4] gate sums
    float* csh  = gsm + 32 * 4;             // [32] cell state (u*4+b)

    const int tid = threadIdx.x;
    const int blk = blockIdx.x;
    const int u0 = blk * UPB;

    // load weight shard: row r = g*8+u  ->  Whh[g*H + u0+u][:]
#pragma unroll
    for (int r = 0; r < 32; ++r) {
        int g = r >> 3, u = r & 7;
        const float* src = Whh + (size_t)(g * HH + u0 + u) * HH;
        *(float4*)(Wsh + r * 1028 + tid * 4) = *(const float4*)(src + tid * 4);
    }
    if (tid < 32) csh[tid] = 0.f;
    for (int i = tid * 4; i < BB * HH; i += 1024)
        *(float4*)(hsh + i) = make_float4(0.f, 0.f, 0.f, 0.f);
    __syncthreads();

    const int j  = tid & 31;   // gate-unit index: g = j>>3, u = j&7
    const int ks = tid >> 5;   // k-slice 0..7 (warp id)

    for (int t = 0; t < TT; ++t) {
        if (t > 0) {
            if (tid < NBLK) {
                volatile int* f = flags + tid;
                while (*f < t) { }
            }
            __syncthreads();
            __threadfence();
            const float* hp = hout + (size_t)(t - 1) * BB * HH;
            for (int i = tid * 4; i < BB * HH; i += 1024)
                *(float4*)(hsh + i) = __ldcg((const float4*)(hp + i));
            __syncthreads();
        }

        // partial dot products: acc[b] = sum_{k in slice} Wsh[j][k] * h[b][k]
        {
            const float* wr = Wsh + j * 1028 + (ks << 7);
            const float* hb = hsh + (ks << 7);
            float a0 = 0.f, a1 = 0.f, a2 = 0.f, a3 = 0.f;
#pragma unroll 8
            for (int k = 0; k < 128; k += 4) {
                float4 wv = *(const float4*)(wr + k);
                float4 x0 = *(const float4*)(hb + k);
                float4 x1 = *(const float4*)(hb + 1024 + k);
                float4 x2 = *(const float4*)(hb + 2048 + k);
                float4 x3 = *(const float4*)(hb + 3072 + k);
                a0 = fmaf(wv.x, x0.x, a0); a0 = fmaf(wv.y, x0.y, a0);
                a0 = fmaf(wv.z, x0.z, a0); a0 = fmaf(wv.w, x0.w, a0);
                a1 = fmaf(wv.x, x1.x, a1); a1 = fmaf(wv.y, x1.y, a1);
                a1 = fmaf(wv.z, x1.z, a1); a1 = fmaf(wv.w, x1.w, a1);
                a2 = fmaf(wv.x, x2.x, a2); a2 = fmaf(wv.y, x2.y, a2);
                a2 = fmaf(wv.z, x2.z, a2); a2 = fmaf(wv.w, x2.w, a2);
                a3 = fmaf(wv.x, x3.x, a3); a3 = fmaf(wv.y, x3.y, a3);
                a3 = fmaf(wv.z, x3.z, a3); a3 = fmaf(wv.w, x3.w, a3);
            }
            *(float4*)(part + ((ks << 5) + j) * 4) = make_float4(a0, a1, a2, a3);
        }
        __syncthreads();

        // reduce across k-slices, add precomputed input gates
        if (tid < 128) {
            int jj = tid >> 2, b = tid & 3;
            float s = 0.f;
#pragma unroll
            for (int q = 0; q < 8; ++q) s += part[((q << 5) + jj) * 4 + b];
            int g = jj >> 3, u = jj & 7;
            s += gates_in[((size_t)t * BB + b) * (4 * HH) + g * HH + u0 + u];
            gsm[jj * 4 + b] = s;
        }
        __syncthreads();

        // LSTM cell for this block's (u,b)
        if (tid < 32) {
            int u = tid >> 2, b = tid & 3;
            float gi = gsm[(0 * 8 + u) * 4 + b];
            float gf = gsm[(1 * 8 + u) * 4 + b];
            float gc = gsm[(2 * 8 + u) * 4 + b];
            float go = gsm[(3 * 8 + u) * 4 + b];
            float c  = csh[tid];
            float cn = sigm(gf) * c + sigm(gi) * tanhf(gc);
            float hn = sigm(go) * tanhf(cn);
            csh[tid] = cn;
            hout[((size_t)t * BB + b) * HH + u0 + u] = hn;
            __threadfence();
        }
        __syncthreads();
        if (tid == 0) {
            __threadfence();
            ((volatile int*)flags)[blk] = t + 1;
        }
    }
}

__global__ void reset_flags_kernel(int* f)
{
    if (threadIdx.x < NBLK) f[threadIdx.x] = 0;
}

// ---------------- LayerNorm + layout change to batch-major ----------------
__global__ __launch_bounds__(256) void layernorm_kernel(
    const float* __restrict__ in,   // [T][B][H]
    const float* __restrict__ w, const float* __restrict__ bv,
    float* __restrict__ out)        // [B][T][H]
{
    int t = blockIdx.x, b = blockIdx.y;
    const float* x = in + ((size_t)t * BB + b) * HH;
    float* o = out + ((size_t)b * TT + t) * HH;
    __shared__ float row[HH];
    __shared__ float red[8];
    __shared__ float stat[2];
    int tid = threadIdx.x;

    float s = 0.f;
    for (int i = tid; i < HH; i += 256) { float v = x[i]; row[i] = v; s += v; }
#pragma unroll
    for (int off = 16; off; off >>= 1) s += __shfl_xor_sync(0xffffffffu, s, off);
    if ((tid & 31) == 0) red[tid >> 5] = s;
    __syncthreads();
    if (tid == 0) {
        float tot = 0.f;
        for (int i = 0; i < 8; ++i) tot += red[i];
        stat[0] = tot * (1.f / HH);
    }
    __syncthreads();
    float mu = stat[0];

    float v2 = 0.f;
    for (int i = tid; i < HH; i += 256) { float d = row[i] - mu; v2 += d * d; }
#pragma unroll
    for (int off = 16; off; off >>= 1) v2 += __shfl_xor_sync(0xffffffffu, v2, off);
    __syncthreads();
    if ((tid & 31) == 0) red[tid >> 5] = v2;
    __syncthreads();
    if (tid == 0) {
        float tot = 0.f;
        for (int i = 0; i < 8; ++i) tot += red[i];
        stat[1] = rsqrtf(tot * (1.f / HH) + 1e-5f);
    }
    __syncthreads();
    float inv = stat[1];
    for (int i = tid; i < HH; i += 256)
        o[i] = (row[i] - mu) * inv * w[i] + bv[i];
}

// ---------------- launch ----------------
extern "C" void kernel_launch(void* const* d_in, const int* in_sizes, int n_in,
                              void* d_out, int out_size)
{
    (void)in_sizes; (void)n_in; (void)out_size;
    const int*   ids = (const int*)d_in[0];
    const float* we  = (const float*)d_in[1];
    const float* pe  = (const float*)d_in[2];
    const float* Wih = (const float*)d_in[3];
    const float* Whh = (const float*)d_in[4];
    const float* bih = (const float*)d_in[5];
    const float* bhh = (const float*)d_in[6];
    const float* lnw = (const float*)d_in[7];
    const float* lnb = (const float*)d_in[8];
    float* out = (float*)d_out;

    float *feats, *gates, *h0, *h1, *xn; int* flags;
    cudaGetSymbolAddress((void**)&feats, g_feats);
    cudaGetSymbolAddress((void**)&gates, g_gates);
    cudaGetSymbolAddress((void**)&h0,    g_h0);
    cudaGetSymbolAddress((void**)&h1,    g_h1);
    cudaGetSymbolAddress((void**)&xn,    g_xn);
    cudaGetSymbolAddress((void**)&flags, g_flags);

    size_t smem = (size_t)(32 * 1028 + 4 * 1024 + 8 * 32 * 4 + 32 * 4 + 32) * sizeof(float);
    cudaFuncSetAttribute(lstm_layer_kernel,
                         cudaFuncAttributeMaxDynamicSharedMemorySize, (int)smem);

    // 1) embedding (time-major)
    embed_kernel<<<dim3(TT, BB), 256>>>(ids, we, pe, feats);

    // 2) layer0 input gates: feats @ W_ih0^T + b
    gemm_nt_kernel<<<dim3(4 * HH / 128, TT * BB / 128), 256>>>(
        feats, Wih, bih, bhh, gates, TT * BB, 4 * HH, HH);

    // 3) layer0 recurrence
    reset_flags_kernel<<<1, NBLK>>>(flags);
    lstm_layer_kernel<<<NBLK, 256, smem>>>(gates, Whh, h0, flags);

    // 4) layer1 input gates: h0 @ W_ih1^T + b
    gemm_nt_kernel<<<dim3(4 * HH / 128, TT * BB / 128), 256>>>(
        h0, Wih + (size_t)4 * HH * HH, bih + 4 * HH, bhh + 4 * HH,
        gates, TT * BB, 4 * HH, HH);

    // 5) layer1 recurrence
    reset_flags_kernel<<<1, NBLK>>>(flags);
    lstm_layer_kernel<<<NBLK, 256, smem>>>(gates, Whh + (size_t)4 * HH * HH, h1, flags);

    // 6) layernorm (also converts to batch-major rows)
    layernorm_kernel<<<dim3(TT, BB), 256>>>(h1, lnw, lnb, xn);

    // 7) tied LM head: logits[b*T+t][v] = xn @ word_emb^T
    gemm_nt_kernel<<<dim3(VV / 128, TT * BB / 128), 256>>>(
        xn, we, nullptr, nullptr, out, TT * BB, VV, HH);
}

// round 7
// speedup vs baseline: 1.6107x; 1.1654x over previous
#include <cuda_runtime.h>
#include <cuda_bf16.h>
#include <cstdint>
#include <math.h>

#define TT 1024
#define BB 4
#define HH 1024
#define VV 32000
#define NBLK 128
#define UPB 8

// ======================= helpers =======================
__device__ __forceinline__ uint32_t smem_to_u32(const void* p) {
    uint32_t a;
    asm("{ .reg .u64 t; cvta.to.shared.u64 t, %1; cvt.u32.u64 %0, t; }" : "=r"(a) : "l"(p));
    return a;
}
__device__ __forceinline__ void cp16(uint32_t dst, const void* src) {
    asm volatile("cp.async.cg.shared.global [%0], [%1], 16;" :: "r"(dst), "l"(src) : "memory");
}
#define CP_COMMIT() asm volatile("cp.async.commit_group;" ::: "memory")
#define CP_WAIT(n)  asm volatile("cp.async.wait_group %0;" :: "n"(n) : "memory")

#define LDSM_X4(r0, r1, r2, r3, addr) \
    asm volatile("ldmatrix.sync.aligned.m8n8.x4.shared.b16 {%0,%1,%2,%3}, [%4];" \
        : "=r"(r0), "=r"(r1), "=r"(r2), "=r"(r3) : "r"(addr))
#define MMA16816(c0, c1, c2, c3, a0, a1, a2, a3, b0, b1) \
    asm volatile("mma.sync.aligned.m16n8k16.row.col.f32.bf16.bf16.f32 " \
        "{%0,%1,%2,%3}, {%4,%5,%6,%7}, {%8,%9}, {%0,%1,%2,%3};" \
        : "+f"(c0), "+f"(c1), "+f"(c2), "+f"(c3) \
        : "r"(a0), "r"(a1), "r"(a2), "r"(a3), "r"(b0), "r"(b1))

// ======================= scratch =======================
__device__ __nv_bfloat16 g_weh[(size_t)VV * HH];
__device__ __nv_bfloat16 g_wel[(size_t)VV * HH];
__device__ __nv_bfloat16 g_wihh[(size_t)2 * 4 * HH * HH];
__device__ __nv_bfloat16 g_wihl[(size_t)2 * 4 * HH * HH];
__device__ __nv_bfloat16 g_fh[(size_t)TT * BB * HH];
__device__ __nv_bfloat16 g_fl[(size_t)TT * BB * HH];
__device__ __nv_bfloat16 g_h0h[(size_t)TT * BB * HH];
__device__ __nv_bfloat16 g_h0l[(size_t)TT * BB * HH];
__device__ __nv_bfloat16 g_xnh[(size_t)TT * BB * HH];
__device__ __nv_bfloat16 g_xnl[(size_t)TT * BB * HH];
__device__ float g_gates[(size_t)TT * BB * 4 * HH];
__device__ float g_h0[(size_t)TT * BB * HH];
__device__ float g_h1[(size_t)TT * BB * HH];
__device__ int   g_flags[NBLK];

__device__ __forceinline__ void split_bf16(float v, __nv_bfloat16& hi, __nv_bfloat16& lo) {
    __nv_bfloat16 h = __float2bfloat16(v);
    hi = h;
    lo = __float2bfloat16(v - __bfloat162float(h));
}

// ======================= fp32 -> bf16 hi/lo split =======================
__global__ __launch_bounds__(256) void convsplit_kernel(
    const float* __restrict__ in, __nv_bfloat16* __restrict__ hi,
    __nv_bfloat16* __restrict__ lo, int n4)
{
    int i = blockIdx.x * blockDim.x + threadIdx.x;
    if (i >= n4) return;
    float4 v = ((const float4*)in)[i];
    __nv_bfloat16 h0, h1, h2, h3, l0, l1, l2, l3;
    split_bf16(v.x, h0, l0); split_bf16(v.y, h1, l1);
    split_bf16(v.z, h2, l2); split_bf16(v.w, h3, l3);
    ((__nv_bfloat162*)hi)[i * 2 + 0] = __nv_bfloat162(h0, h1);
    ((__nv_bfloat162*)hi)[i * 2 + 1] = __nv_bfloat162(h2, h3);
    ((__nv_bfloat162*)lo)[i * 2 + 0] = __nv_bfloat162(l0, l1);
    ((__nv_bfloat162*)lo)[i * 2 + 1] = __nv_bfloat162(l2, l3);
}

// ======================= embedding -> bf16 split, time-major =======================
__global__ __launch_bounds__(256) void embed_kernel(
    const int* __restrict__ ids, const float* __restrict__ we,
    const float* __restrict__ pe, __nv_bfloat16* __restrict__ oh,
    __nv_bfloat16* __restrict__ ol)
{
    int t = blockIdx.x, b = blockIdx.y;
    int id = ids[b * TT + t];
    const float4* w = (const float4*)(we + (size_t)id * HH);
    const float4* p = (const float4*)(pe + (size_t)t * HH);
    size_t row = ((size_t)t * BB + b) * HH;
    for (int i = threadIdx.x; i < HH / 4; i += blockDim.x) {
        float4 a = w[i], c = p[i];
        float4 v = make_float4(a.x + c.x, a.y + c.y, a.z + c.z, a.w + c.w);
        __nv_bfloat16 h0, h1, h2, h3, l0, l1, l2, l3;
        split_bf16(v.x, h0, l0); split_bf16(v.y, h1, l1);
        split_bf16(v.z, h2, l2); split_bf16(v.w, h3, l3);
        ((__nv_bfloat162*)(oh + row))[i * 2 + 0] = __nv_bfloat162(h0, h1);
        ((__nv_bfloat162*)(oh + row))[i * 2 + 1] = __nv_bfloat162(h2, h3);
        ((__nv_bfloat162*)(ol + row))[i * 2 + 0] = __nv_bfloat162(l0, l1);
        ((__nv_bfloat162*)(ol + row))[i * 2 + 1] = __nv_bfloat162(l2, l3);
    }
}

// ======================= HMMA split-bf16 NT GEMM =======================
// C[m][n] = sum_k A[m][k]*B[n][k] (+ bias0[n]+bias1[n]); K = 1024 fixed.
// CTA tile 128x128, K-chunk 32. 8 warps, each 32(m) x 64(n) via m16n8k16.
// B is [n][k] row-major == mma.row.col's col-major B -> plain (non-trans) ldmatrix.
#define TSTRIDE 40
#define TILE_E  (128 * TSTRIDE)
#define TILE_BYTES (TILE_E * 2)            // 10240
#define BUF_BYTES (4 * TILE_BYTES)         // 40960
#define GSMEM (2 * BUF_BYTES)              // 81920

__global__ __launch_bounds__(256) void gemm_hmma_kernel(
    const __nv_bfloat16* __restrict__ Ah, const __nv_bfloat16* __restrict__ Al,
    const __nv_bfloat16* __restrict__ Bh, const __nv_bfloat16* __restrict__ Bl,
    const float* __restrict__ bias0, const float* __restrict__ bias1,
    float* __restrict__ C, int N)
{
    extern __shared__ __nv_bfloat16 sm[];
    const uint32_t sbase = smem_to_u32(sm);
    const int tid = threadIdx.x;
    const int lane = tid & 31;
    const int wid = tid >> 5;
    const int wm = wid & 3;          // warp row block (32 rows)
    const int wn = wid >> 2;         // warp col block (64 cols)
    const int bn = blockIdx.x << 7;
    const int bm = blockIdx.y << 7;

    float acc[2][8][4];
#pragma unroll
    for (int mt = 0; mt < 2; ++mt)
#pragma unroll
        for (int nt = 0; nt < 8; ++nt)
#pragma unroll
            for (int q = 0; q < 4; ++q) acc[mt][nt][q] = 0.f;

    const __nv_bfloat16* srcs[4] = { Ah, Al, Bh, Bl };
    const int rb[4] = { bm, bm, bn, bn };

    auto load_chunk = [&](int c) {
        uint32_t buf = sbase + (c & 1) * BUF_BYTES;
#pragma unroll
        for (int tsel = 0; tsel < 4; ++tsel) {
            uint32_t dst = buf + tsel * TILE_BYTES;
            const __nv_bfloat16* base = srcs[tsel];
#pragma unroll
            for (int i = 0; i < 2; ++i) {
                int s = tid + (i << 8);              // 0..511
                int row = s >> 2, k8 = s & 3;        // row 0..127, 8-elem group
                cp16(dst + row * (TSTRIDE * 2) + k8 * 16,
                     base + (size_t)(rb[tsel] + row) * 1024 + c * 32 + k8 * 8);
            }
        }
        CP_COMMIT();
    };

    load_chunk(0);

    for (int c = 0; c < 32; ++c) {
        if (c < 31) { load_chunk(c + 1); CP_WAIT(1); }
        else        { CP_WAIT(0); }
        __syncthreads();

        uint32_t buf = sbase + (c & 1) * BUF_BYTES;
        // per-lane ldmatrix source rows (elements)
        const int a_r = (lane & 15);
        const int a_k = (lane >> 4) << 3;                  // lanes 16-31: k+8 matrices
        const int b_n = ((lane >> 4) << 3) + (lane & 7);   // lanes 0-15: n0-7, 16-31: n8-15
        const int b_k = ((lane >> 3) & 1) << 3;            // lanes 8-15/24-31: k+8

#pragma unroll
        for (int ks = 0; ks < 2; ++ks) {
            const int kbase = ks << 4;
            uint32_t ah[2][4], al[2][4], bh[16], bl[16];
#pragma unroll
            for (int mt = 0; mt < 2; ++mt) {
                int row = wm * 32 + mt * 16 + a_r;
                uint32_t addr = buf + (row * TSTRIDE + kbase + a_k) * 2;
                LDSM_X4(ah[mt][0], ah[mt][1], ah[mt][2], ah[mt][3], addr);
                LDSM_X4(al[mt][0], al[mt][1], al[mt][2], al[mt][3], addr + TILE_BYTES);
            }
#pragma unroll
            for (int np = 0; np < 4; ++np) {
                int nrow = wn * 64 + np * 16 + b_n;
                uint32_t addr = buf + 2 * TILE_BYTES + (nrow * TSTRIDE + kbase + b_k) * 2;
                // non-trans: r0/r1 = b0/b1 of n-tile(2*np), r2/r3 = n-tile(2*np+1)
                LDSM_X4(bh[np * 4 + 0], bh[np * 4 + 1], bh[np * 4 + 2], bh[np * 4 + 3], addr);
                LDSM_X4(bl[np * 4 + 0], bl[np * 4 + 1], bl[np * 4 + 2], bl[np * 4 + 3],
                        addr + TILE_BYTES);
            }
#pragma unroll
            for (int mt = 0; mt < 2; ++mt)
#pragma unroll
                for (int nt = 0; nt < 8; ++nt) {
                    float* cc = acc[mt][nt];
                    MMA16816(cc[0], cc[1], cc[2], cc[3],
                             ah[mt][0], ah[mt][1], ah[mt][2], ah[mt][3],
                             bh[nt * 2], bh[nt * 2 + 1]);
                    MMA16816(cc[0], cc[1], cc[2], cc[3],
                             al[mt][0], al[mt][1], al[mt][2], al[mt][3],
                             bh[nt * 2], bh[nt * 2 + 1]);
                    MMA16816(cc[0], cc[1], cc[2], cc[3],
                             ah[mt][0], ah[mt][1], ah[mt][2], ah[mt][3],
                             bl[nt * 2], bl[nt * 2 + 1]);
                }
        }
        __syncthreads();
    }

    // epilogue
#pragma unroll
    for (int mt = 0; mt < 2; ++mt) {
        int row0 = bm + wm * 32 + mt * 16 + (lane >> 2);
#pragma unroll
        for (int nt = 0; nt < 8; ++nt) {
            int col = bn + wn * 64 + nt * 8 + ((lane & 3) << 1);
            float b0v = 0.f, b1v = 0.f;
            if (bias0) {
                b0v = bias0[col] + bias1[col];
                b1v = bias0[col + 1] + bias1[col + 1];
            }
            float* c0 = C + (size_t)row0 * N + col;
            float* c1 = C + (size_t)(row0 + 8) * N + col;
            *(float2*)c0 = make_float2(acc[mt][nt][0] + b0v, acc[mt][nt][1] + b1v);
            *(float2*)c1 = make_float2(acc[mt][nt][2] + b0v, acc[mt][nt][3] + b1v);
        }
    }
}

// ======================= persistent LSTM recurrence (known-good) =======================
__device__ __forceinline__ float sigm(float x) { return 1.f / (1.f + expf(-x)); }

__global__ __launch_bounds__(256) void lstm_layer_kernel(
    const float* __restrict__ gates_in, const float* __restrict__ Whh,
    float* __restrict__ hout, int* flags)
{
    extern __shared__ float smf[];
    float* Wsh  = smf;
    float* hsh  = Wsh + 32 * 1028;
    float* part = hsh + 4 * 1024;
    float* gsm  = part + 8 * 32 * 4;
    float* csh  = gsm + 32 * 4;

    const int tid = threadIdx.x;
    const int blk = blockIdx.x;
    const int u0 = blk * UPB;

#pragma unroll
    for (int r = 0; r < 32; ++r) {
        int g = r >> 3, u = r & 7;
        const float* src = Whh + (size_t)(g * HH + u0 + u) * HH;
        *(float4*)(Wsh + r * 1028 + tid * 4) = *(const float4*)(src + tid * 4);
    }
    if (tid < 32) csh[tid] = 0.f;
    for (int i = tid * 4; i < BB * HH; i += 1024)
        *(float4*)(hsh + i) = make_float4(0.f, 0.f, 0.f, 0.f);
    __syncthreads();

    const int j  = tid & 31;
    const int ks = tid >> 5;

    for (int t = 0; t < TT; ++t) {
        if (t > 0) {
            if (tid < NBLK) {
                volatile int* f = flags + tid;
                while (*f < t) { }
            }
            __syncthreads();
            __threadfence();
            const float* hp = hout + (size_t)(t - 1) * BB * HH;
            for (int i = tid * 4; i < BB * HH; i += 1024)
                *(float4*)(hsh + i) = __ldcg((const float4*)(hp + i));
            __syncthreads();
        }
        {
            const float* wr = Wsh + j * 1028 + (ks << 7);
            const float* hb = hsh + (ks << 7);
            float a0 = 0.f, a1 = 0.f, a2 = 0.f, a3 = 0.f;
#pragma unroll 8
            for (int k = 0; k < 128; k += 4) {
                float4 wv = *(const float4*)(wr + k);
                float4 x0 = *(const float4*)(hb + k);
                float4 x1 = *(const float4*)(hb + 1024 + k);
                float4 x2 = *(const float4*)(hb + 2048 + k);
                float4 x3 = *(const float4*)(hb + 3072 + k);
                a0 = fmaf(wv.x, x0.x, a0); a0 = fmaf(wv.y, x0.y, a0);
                a0 = fmaf(wv.z, x0.z, a0); a0 = fmaf(wv.w, x0.w, a0);
                a1 = fmaf(wv.x, x1.x, a1); a1 = fmaf(wv.y, x1.y, a1);
                a1 = fmaf(wv.z, x1.z, a1); a1 = fmaf(wv.w, x1.w, a1);
                a2 = fmaf(wv.x, x2.x, a2); a2 = fmaf(wv.y, x2.y, a2);
                a2 = fmaf(wv.z, x2.z, a2); a2 = fmaf(wv.w, x2.w, a2);
                a3 = fmaf(wv.x, x3.x, a3); a3 = fmaf(wv.y, x3.y, a3);
                a3 = fmaf(wv.z, x3.z, a3); a3 = fmaf(wv.w, x3.w, a3);
            }
            *(float4*)(part + ((ks << 5) + j) * 4) = make_float4(a0, a1, a2, a3);
        }
        __syncthreads();
        if (tid < 128) {
            int jj = tid >> 2, b = tid & 3;
            float s = 0.f;
#pragma unroll
            for (int q = 0; q < 8; ++q) s += part[((q << 5) + jj) * 4 + b];
            int g = jj >> 3, u = jj & 7;
            s += gates_in[((size_t)t * BB + b) * (4 * HH) + g * HH + u0 + u];
            gsm[jj * 4 + b] = s;
        }
        __syncthreads();
        if (tid < 32) {
            int u = tid >> 2, b = tid & 3;
            float gi = gsm[(0 * 8 + u) * 4 + b];
            float gf = gsm[(1 * 8 + u) * 4 + b];
            float gc = gsm[(2 * 8 + u) * 4 + b];
            float go = gsm[(3 * 8 + u) * 4 + b];
            float cc = csh[tid];
            float cn = sigm(gf) * cc + sigm(gi) * tanhf(gc);
            float hn = sigm(go) * tanhf(cn);
            csh[tid] = cn;
            hout[((size_t)t * BB + b) * HH + u0 + u] = hn;
            __threadfence();
        }
        __syncthreads();
        if (tid == 0) {
            __threadfence();
            ((volatile int*)flags)[blk] = t + 1;
        }
    }
}

__global__ void reset_flags_kernel(int* f)
{
    if (threadIdx.x < NBLK) f[threadIdx.x] = 0;
}

// ======================= LayerNorm -> bf16 split, batch-major =======================
__global__ __launch_bounds__(256) void layernorm_kernel(
    const float* __restrict__ in, const float* __restrict__ w,
    const float* __restrict__ bv, __nv_bfloat16* __restrict__ oh,
    __nv_bfloat16* __restrict__ ol)
{
    int t = blockIdx.x, b = blockIdx.y;
    const float* x = in + ((size_t)t * BB + b) * HH;
    size_t orow = ((size_t)b * TT + t) * HH;
    __shared__ float row[HH];
    __shared__ float red[8];
    __shared__ float stat[2];
    int tid = threadIdx.x;

    float s = 0.f;
    for (int i = tid; i < HH; i += 256) { float v = x[i]; row[i] = v; s += v; }
#pragma unroll
    for (int off = 16; off; off >>= 1) s += __shfl_xor_sync(0xffffffffu, s, off);
    if ((tid & 31) == 0) red[tid >> 5] = s;
    __syncthreads();
    if (tid == 0) {
        float tot = 0.f;
        for (int i = 0; i < 8; ++i) tot += red[i];
        stat[0] = tot * (1.f / HH);
    }
    __syncthreads();
    float mu = stat[0];
    float v2 = 0.f;
    for (int i = tid; i < HH; i += 256) { float d = row[i] - mu; v2 += d * d; }
#pragma unroll
    for (int off = 16; off; off >>= 1) v2 += __shfl_xor_sync(0xffffffffu, v2, off);
    __syncthreads();
    if ((tid & 31) == 0) red[tid >> 5] = v2;
    __syncthreads();
    if (tid == 0) {
        float tot = 0.f;
        for (int i = 0; i < 8; ++i) tot += red[i];
        stat[1] = rsqrtf(tot * (1.f / HH) + 1e-5f);
    }
    __syncthreads();
    float inv = stat[1];
    for (int i = tid; i < HH; i += 256) {
        float v = (row[i] - mu) * inv * w[i] + bv[i];
        __nv_bfloat16 hi, lo;
        split_bf16(v, hi, lo);
        oh[orow + i] = hi;
        ol[orow + i] = lo;
    }
}

// ======================= launch =======================
extern "C" void kernel_launch(void* const* d_in, const int* in_sizes, int n_in,
                              void* d_out, int out_size)
{
    (void)in_sizes; (void)n_in; (void)out_size;
    const int*   ids = (const int*)d_in[0];
    const float* we  = (const float*)d_in[1];
    const float* pe  = (const float*)d_in[2];
    const float* Wih = (const float*)d_in[3];
    const float* Whh = (const float*)d_in[4];
    const float* bih = (const float*)d_in[5];
    const float* bhh = (const float*)d_in[6];
    const float* lnw = (const float*)d_in[7];
    const float* lnb = (const float*)d_in[8];
    float* out = (float*)d_out;

    __nv_bfloat16 *weh, *wel, *wihh, *wihl, *fh, *fl, *h0h, *h0l, *xnh, *xnl;
    float *gates, *h0, *h1; int* flags;
    cudaGetSymbolAddress((void**)&weh,  g_weh);
    cudaGetSymbolAddress((void**)&wel,  g_wel);
    cudaGetSymbolAddress((void**)&wihh, g_wihh);
    cudaGetSymbolAddress((void**)&wihl, g_wihl);
    cudaGetSymbolAddress((void**)&fh,   g_fh);
    cudaGetSymbolAddress((void**)&fl,   g_fl);
    cudaGetSymbolAddress((void**)&h0h,  g_h0h);
    cudaGetSymbolAddress((void**)&h0l,  g_h0l);
    cudaGetSymbolAddress((void**)&xnh,  g_xnh);
    cudaGetSymbolAddress((void**)&xnl,  g_xnl);
    cudaGetSymbolAddress((void**)&gates, g_gates);
    cudaGetSymbolAddress((void**)&h0,    g_h0);
    cudaGetSymbolAddress((void**)&h1,    g_h1);
    cudaGetSymbolAddress((void**)&flags, g_flags);

    size_t lsmem = (size_t)(32 * 1028 + 4 * 1024 + 8 * 32 * 4 + 32 * 4 + 32) * sizeof(float);
    cudaFuncSetAttribute(lstm_layer_kernel,
                         cudaFuncAttributeMaxDynamicSharedMemorySize, (int)lsmem);
    cudaFuncSetAttribute(gemm_hmma_kernel,
                         cudaFuncAttributeMaxDynamicSharedMemorySize, GSMEM);

    // weight/input splits
    convsplit_kernel<<<(VV * HH / 4 + 255) / 256, 256>>>(we, weh, wel, VV * HH / 4);
    convsplit_kernel<<<(2 * 4 * HH * HH / 4 + 255) / 256, 256>>>(Wih, wihh, wihl,
                                                                 2 * 4 * HH * HH / 4);
    embed_kernel<<<dim3(TT, BB), 256>>>(ids, we, pe, fh, fl);

    // layer0 input gates: [T*B,4H] = feats @ W_ih0^T + b
    gemm_hmma_kernel<<<dim3(4 * HH / 128, TT * BB / 128), 256, GSMEM>>>(
        fh, fl, wihh, wihl, bih, bhh, gates, 4 * HH);
    reset_flags_kernel<<<1, NBLK>>>(flags);
    lstm_layer_kernel<<<NBLK, 256, lsmem>>>(gates, Whh, h0, flags);

    // layer1
    convsplit_kernel<<<(TT * BB * HH / 4 + 255) / 256, 256>>>(h0, h0h, h0l, TT * BB * HH / 4);
    gemm_hmma_kernel<<<dim3(4 * HH / 128, TT * BB / 128), 256, GSMEM>>>(
        h0h, h0l, wihh + (size_t)4 * HH * HH, wihl + (size_t)4 * HH * HH,
        bih + 4 * HH, bhh + 4 * HH, gates, 4 * HH);
    reset_flags_kernel<<<1, NBLK>>>(flags);
    lstm_layer_kernel<<<NBLK, 256, lsmem>>>(gates, Whh + (size_t)4 * HH * HH, h1, flags);

    // layernorm + head
    layernorm_kernel<<<dim3(TT, BB), 256>>>(h1, lnw, lnb, xnh, xnl);
    gemm_hmma_kernel<<<dim3(VV / 128, TT * BB / 128), 256, GSMEM>>>(
        xnh, xnl, weh, wel, nullptr, nullptr, out, VV);
}

// round 8
// speedup vs baseline: 2.5925x; 1.6096x over previous
#include <cuda_runtime.h>
#include <cuda_bf16.h>
#include <cstdint>
#include <math.h>

#define TT 1024
#define BB 4
#define HH 1024
#define VV 32000
#define NBLK 128
#define UPB 8

// ======================= helpers =======================
__device__ __forceinline__ uint32_t smem_to_u32(const void* p) {
    uint32_t a;
    asm("{ .reg .u64 t; cvta.to.shared.u64 t, %1; cvt.u32.u64 %0, t; }" : "=r"(a) : "l"(p));
    return a;
}
__device__ __forceinline__ void cp16(uint32_t dst, const void* src) {
    asm volatile("cp.async.cg.shared.global [%0], [%1], 16;" :: "r"(dst), "l"(src) : "memory");
}
#define CP_COMMIT() asm volatile("cp.async.commit_group;" ::: "memory")
#define CP_WAIT(n)  asm volatile("cp.async.wait_group %0;" :: "n"(n) : "memory")

#define LDSM_X4(r0, r1, r2, r3, addr) \
    asm volatile("ldmatrix.sync.aligned.m8n8.x4.shared.b16 {%0,%1,%2,%3}, [%4];" \
        : "=r"(r0), "=r"(r1), "=r"(r2), "=r"(r3) : "r"(addr))
#define MMA16816(c0, c1, c2, c3, a0, a1, a2, a3, b0, b1) \
    asm volatile("mma.sync.aligned.m16n8k16.row.col.f32.bf16.bf16.f32 " \
        "{%0,%1,%2,%3}, {%4,%5,%6,%7}, {%8,%9}, {%0,%1,%2,%3};" \
        : "+f"(c0), "+f"(c1), "+f"(c2), "+f"(c3) \
        : "r"(a0), "r"(a1), "r"(a2), "r"(a3), "r"(b0), "r"(b1))

// ======================= scratch =======================
__device__ __nv_bfloat16 g_weh[(size_t)VV * HH];
__device__ __nv_bfloat16 g_wel[(size_t)VV * HH];
__device__ __nv_bfloat16 g_wihh[(size_t)2 * 4 * HH * HH];
__device__ __nv_bfloat16 g_wihl[(size_t)2 * 4 * HH * HH];
__device__ __nv_bfloat16 g_fh[(size_t)TT * BB * HH];
__device__ __nv_bfloat16 g_fl[(size_t)TT * BB * HH];
__device__ __nv_bfloat16 g_h0h[(size_t)TT * BB * HH];
__device__ __nv_bfloat16 g_h0l[(size_t)TT * BB * HH];
__device__ __nv_bfloat16 g_xnh[(size_t)TT * BB * HH];
__device__ __nv_bfloat16 g_xnl[(size_t)TT * BB * HH];
__device__ float g_gates[(size_t)TT * BB * 4 * HH];
__device__ float g_h0[(size_t)TT * BB * HH];
__device__ float g_h1[(size_t)TT * BB * HH];
__device__ unsigned g_counter;

__device__ __forceinline__ void split_bf16(float v, __nv_bfloat16& hi, __nv_bfloat16& lo) {
    __nv_bfloat16 h = __float2bfloat16(v);
    hi = h;
    lo = __float2bfloat16(v - __bfloat162float(h));
}

// ======================= fp32 -> bf16 hi/lo split =======================
__global__ __launch_bounds__(256) void convsplit_kernel(
    const float* __restrict__ in, __nv_bfloat16* __restrict__ hi,
    __nv_bfloat16* __restrict__ lo, int n4)
{
    int i = blockIdx.x * blockDim.x + threadIdx.x;
    if (i >= n4) return;
    float4 v = ((const float4*)in)[i];
    __nv_bfloat16 h0, h1, h2, h3, l0, l1, l2, l3;
    split_bf16(v.x, h0, l0); split_bf16(v.y, h1, l1);
    split_bf16(v.z, h2, l2); split_bf16(v.w, h3, l3);
    ((__nv_bfloat162*)hi)[i * 2 + 0] = __nv_bfloat162(h0, h1);
    ((__nv_bfloat162*)hi)[i * 2 + 1] = __nv_bfloat162(h2, h3);
    ((__nv_bfloat162*)lo)[i * 2 + 0] = __nv_bfloat162(l0, l1);
    ((__nv_bfloat162*)lo)[i * 2 + 1] = __nv_bfloat162(l2, l3);
}

// ======================= embedding -> bf16 split, time-major =======================
__global__ __launch_bounds__(256) void embed_kernel(
    const int* __restrict__ ids, const float* __restrict__ we,
    const float* __restrict__ pe, __nv_bfloat16* __restrict__ oh,
    __nv_bfloat16* __restrict__ ol)
{
    int t = blockIdx.x, b = blockIdx.y;
    int id = ids[b * TT + t];
    const float4* w = (const float4*)(we + (size_t)id * HH);
    const float4* p = (const float4*)(pe + (size_t)t * HH);
    size_t row = ((size_t)t * BB + b) * HH;
    for (int i = threadIdx.x; i < HH / 4; i += blockDim.x) {
        float4 a = w[i], c = p[i];
        float4 v = make_float4(a.x + c.x, a.y + c.y, a.z + c.z, a.w + c.w);
        __nv_bfloat16 h0, h1, h2, h3, l0, l1, l2, l3;
        split_bf16(v.x, h0, l0); split_bf16(v.y, h1, l1);
        split_bf16(v.z, h2, l2); split_bf16(v.w, h3, l3);
        ((__nv_bfloat162*)(oh + row))[i * 2 + 0] = __nv_bfloat162(h0, h1);
        ((__nv_bfloat162*)(oh + row))[i * 2 + 1] = __nv_bfloat162(h2, h3);
        ((__nv_bfloat162*)(ol + row))[i * 2 + 0] = __nv_bfloat162(l0, l1);
        ((__nv_bfloat162*)(ol + row))[i * 2 + 1] = __nv_bfloat162(l2, l3);
    }
}

// ======================= HMMA split-bf16 NT GEMM (known-good) =======================
#define TSTRIDE 40
#define TILE_E  (128 * TSTRIDE)
#define TILE_BYTES (TILE_E * 2)            // 10240
#define BUF_BYTES (4 * TILE_BYTES)         // 40960
#define GSMEM (2 * BUF_BYTES)              // 81920

__global__ __launch_bounds__(256) void gemm_hmma_kernel(
    const __nv_bfloat16* __restrict__ Ah, const __nv_bfloat16* __restrict__ Al,
    const __nv_bfloat16* __restrict__ Bh, const __nv_bfloat16* __restrict__ Bl,
    const float* __restrict__ bias0, const float* __restrict__ bias1,
    float* __restrict__ C, int N)
{
    extern __shared__ __nv_bfloat16 sm[];
    const uint32_t sbase = smem_to_u32(sm);
    const int tid = threadIdx.x;
    const int lane = tid & 31;
    const int wid = tid >> 5;
    const int wm = wid & 3;
    const int wn = wid >> 2;
    const int bn = blockIdx.x << 7;
    const int bm = blockIdx.y << 7;

    float acc[2][8][4];
#pragma unroll
    for (int mt = 0; mt < 2; ++mt)
#pragma unroll
        for (int nt = 0; nt < 8; ++nt)
#pragma unroll
            for (int q = 0; q < 4; ++q) acc[mt][nt][q] = 0.f;

    const __nv_bfloat16* srcs[4] = { Ah, Al, Bh, Bl };
    const int rb[4] = { bm, bm, bn, bn };

    auto load_chunk = [&](int c) {
        uint32_t buf = sbase + (c & 1) * BUF_BYTES;
#pragma unroll
        for (int tsel = 0; tsel < 4; ++tsel) {
            uint32_t dst = buf + tsel * TILE_BYTES;
            const __nv_bfloat16* base = srcs[tsel];
#pragma unroll
            for (int i = 0; i < 2; ++i) {
                int s = tid + (i << 8);
                int row = s >> 2, k8 = s & 3;
                cp16(dst + row * (TSTRIDE * 2) + k8 * 16,
                     base + (size_t)(rb[tsel] + row) * 1024 + c * 32 + k8 * 8);
            }
        }
        CP_COMMIT();
    };

    load_chunk(0);

    for (int c = 0; c < 32; ++c) {
        if (c < 31) { load_chunk(c + 1); CP_WAIT(1); }
        else        { CP_WAIT(0); }
        __syncthreads();

        uint32_t buf = sbase + (c & 1) * BUF_BYTES;
        const int a_r = (lane & 15);
        const int a_k = (lane >> 4) << 3;
        const int b_n = ((lane >> 4) << 3) + (lane & 7);
        const int b_k = ((lane >> 3) & 1) << 3;

#pragma unroll
        for (int ks = 0; ks < 2; ++ks) {
            const int kbase = ks << 4;
            uint32_t ah[2][4], al[2][4], bh[16], bl[16];
#pragma unroll
            for (int mt = 0; mt < 2; ++mt) {
                int row = wm * 32 + mt * 16 + a_r;
                uint32_t addr = buf + (row * TSTRIDE + kbase + a_k) * 2;
                LDSM_X4(ah[mt][0], ah[mt][1], ah[mt][2], ah[mt][3], addr);
                LDSM_X4(al[mt][0], al[mt][1], al[mt][2], al[mt][3], addr + TILE_BYTES);
            }
#pragma unroll
            for (int np = 0; np < 4; ++np) {
                int nrow = wn * 64 + np * 16 + b_n;
                uint32_t addr = buf + 2 * TILE_BYTES + (nrow * TSTRIDE + kbase + b_k) * 2;
                LDSM_X4(bh[np * 4 + 0], bh[np * 4 + 1], bh[np * 4 + 2], bh[np * 4 + 3], addr);
                LDSM_X4(bl[np * 4 + 0], bl[np * 4 + 1], bl[np * 4 + 2], bl[np * 4 + 3],
                        addr + TILE_BYTES);
            }
#pragma unroll
            for (int mt = 0; mt < 2; ++mt)
#pragma unroll
                for (int nt = 0; nt < 8; ++nt) {
                    float* cc = acc[mt][nt];
                    MMA16816(cc[0], cc[1], cc[2], cc[3],
                             ah[mt][0], ah[mt][1], ah[mt][2], ah[mt][3],
                             bh[nt * 2], bh[nt * 2 + 1]);
                    MMA16816(cc[0], cc[1], cc[2], cc[3],
                             al[mt][0], al[mt][1], al[mt][2], al[mt][3],
                             bh[nt * 2], bh[nt * 2 + 1]);
                    MMA16816(cc[0], cc[1], cc[2], cc[3],
                             ah[mt][0], ah[mt][1], ah[mt][2], ah[mt][3],
                             bl[nt * 2], bl[nt * 2 + 1]);
                }
        }
        __syncthreads();
    }

#pragma unroll
    for (int mt = 0; mt < 2; ++mt) {
        int row0 = bm + wm * 32 + mt * 16 + (lane >> 2);
#pragma unroll
        for (int nt = 0; nt < 8; ++nt) {
            int col = bn + wn * 64 + nt * 8 + ((lane & 3) << 1);
            float b0v = 0.f, b1v = 0.f;
            if (bias0) {
                b0v = bias0[col] + bias1[col];
                b1v = bias0[col + 1] + bias1[col + 1];
            }
            float* c0 = C + (size_t)row0 * N + col;
            float* c1 = C + (size_t)(row0 + 8) * N + col;
            *(float2*)c0 = make_float2(acc[mt][nt][0] + b0v, acc[mt][nt][1] + b1v);
            *(float2*)c1 = make_float2(acc[mt][nt][2] + b0v, acc[mt][nt][3] + b1v);
        }
    }
}

// ======================= persistent LSTM recurrence =======================
// NEW sync scheme: single monotonic arrival counter.
//  arrive: h stores -> __syncthreads -> tid0: red.release.gpu.add(counter, 1)
//  wait:   tid0 spins ld.acquire.gpu until counter >= NBLK*t -> __syncthreads
// gates_in[t] is prefetched into a register BEFORE the wait (independent of h).
__device__ __forceinline__ float sigm(float x) { return 1.f / (1.f + expf(-x)); }

__global__ __launch_bounds__(256) void lstm_layer_kernel(
    const float* __restrict__ gates_in, const float* __restrict__ Whh,
    float* __restrict__ hout, unsigned* counter)
{
    extern __shared__ float smf[];
    float* Wsh  = smf;                      // [32][1028]
    float* hsh  = Wsh + 32 * 1028;          // [4][1024]
    float* part = hsh + 4 * 1024;           // [8][32][4]
    float* gsm  = part + 8 * 32 * 4;        // [32][4]
    float* csh  = gsm + 32 * 4;             // [32]

    const int tid = threadIdx.x;
    const int blk = blockIdx.x;
    const int u0 = blk * UPB;

#pragma unroll
    for (int r = 0; r < 32; ++r) {
        int g = r >> 3, u = r & 7;
        const float* src = Whh + (size_t)(g * HH + u0 + u) * HH;
        *(float4*)(Wsh + r * 1028 + tid * 4) = *(const float4*)(src + tid * 4);
    }
    if (tid < 32) csh[tid] = 0.f;
    for (int i = tid * 4; i < BB * HH; i += 1024)
        *(float4*)(hsh + i) = make_float4(0.f, 0.f, 0.f, 0.f);
    __syncthreads();

    const int j  = tid & 31;
    const int ks = tid >> 5;
    // gate-input address for the reduce stage (tid < 128)
    const int jj = tid >> 2, bb = tid & 3;
    const int gg = jj >> 3, uu = jj & 7;
    const float* gptr = gates_in + (size_t)bb * (4 * HH) + gg * HH + u0 + uu;

    for (int t = 0; t < TT; ++t) {
        // prefetch this step's gate input (latency hides under the barrier wait)
        float gin = 0.f;
        if (tid < 128) gin = __ldg(gptr + (size_t)t * BB * 4 * HH);

        if (t > 0) {
            if (tid == 0) {
                unsigned tgt = (unsigned)NBLK * (unsigned)t;
                unsigned v;
                do {
                    asm volatile("ld.acquire.gpu.global.u32 %0, [%1];"
                                 : "=r"(v) : "l"(counter));
                } while (v < tgt);
            }
            __syncthreads();
            const float* hp = hout + (size_t)(t - 1) * BB * HH;
            for (int i = tid * 4; i < BB * HH; i += 1024)
                *(float4*)(hsh + i) = __ldcg((const float4*)(hp + i));
            __syncthreads();
        }

        // partial dot products: acc[b] = sum_{k in slice} Wsh[j][k] * h[b][k]
        {
            const float* wr = Wsh + j * 1028 + (ks << 7);
            const float* hb = hsh + (ks << 7);
            float a0 = 0.f, a1 = 0.f, a2 = 0.f, a3 = 0.f;
#pragma unroll 8
            for (int k = 0; k < 128; k += 4) {
                float4 wv = *(const float4*)(wr + k);
                float4 x0 = *(const float4*)(hb + k);
                float4 x1 = *(const float4*)(hb + 1024 + k);
                float4 x2 = *(const float4*)(hb + 2048 + k);
                float4 x3 = *(const float4*)(hb + 3072 + k);
                a0 = fmaf(wv.x, x0.x, a0); a0 = fmaf(wv.y, x0.y, a0);
                a0 = fmaf(wv.z, x0.z, a0); a0 = fmaf(wv.w, x0.w, a0);
                a1 = fmaf(wv.x, x1.x, a1); a1 = fmaf(wv.y, x1.y, a1);
                a1 = fmaf(wv.z, x1.z, a1); a1 = fmaf(wv.w, x1.w, a1);
                a2 = fmaf(wv.x, x2.x, a2); a2 = fmaf(wv.y, x2.y, a2);
                a2 = fmaf(wv.z, x2.z, a2); a2 = fmaf(wv.w, x2.w, a2);
                a3 = fmaf(wv.x, x3.x, a3); a3 = fmaf(wv.y, x3.y, a3);
                a3 = fmaf(wv.z, x3.z, a3); a3 = fmaf(wv.w, x3.w, a3);
            }
            *(float4*)(part + ((ks << 5) + j) * 4) = make_float4(a0, a1, a2, a3);
        }
        __syncthreads();

        if (tid < 128) {
            float s = gin;
#pragma unroll
            for (int q = 0; q < 8; ++q) s += part[((q << 5) + jj) * 4 + bb];
            gsm[jj * 4 + bb] = s;
        }
        __syncthreads();

        if (tid < 32) {
            int u = tid >> 2, b = tid & 3;
            float gi = gsm[(0 * 8 + u) * 4 + b];
            float gf = gsm[(1 * 8 + u) * 4 + b];
            float gc = gsm[(2 * 8 + u) * 4 + b];
            float go = gsm[(3 * 8 + u) * 4 + b];
            float cc = csh[tid];
            float cn = sigm(gf) * cc + sigm(gi) * tanhf(gc);
            float hn = sigm(go) * tanhf(cn);
            csh[tid] = cn;
            hout[((size_t)t * BB + b) * HH + u0 + u] = hn;
        }
        __syncthreads();   // all h-stores of this block happen-before tid0's release
        if (tid == 0) {
            asm volatile("red.release.gpu.global.add.u32 [%0], %1;"
                         :: "l"(counter), "r"(1u) : "memory");
        }
    }
}

__global__ void reset_counter_kernel(unsigned* c)
{
    if (threadIdx.x == 0) *c = 0u;
}

// ======================= LayerNorm -> bf16 split, batch-major =======================
__global__ __launch_bounds__(256) void layernorm_kernel(
    const float* __restrict__ in, const float* __restrict__ w,
    const float* __restrict__ bv, __nv_bfloat16* __restrict__ oh,
    __nv_bfloat16* __restrict__ ol)
{
    int t = blockIdx.x, b = blockIdx.y;
    const float* x = in + ((size_t)t * BB + b) * HH;
    size_t orow = ((size_t)b * TT + t) * HH;
    __shared__ float row[HH];
    __shared__ float red[8];
    __shared__ float stat[2];
    int tid = threadIdx.x;

    float s = 0.f;
    for (int i = tid; i < HH; i += 256) { float v = x[i]; row[i] = v; s += v; }
#pragma unroll
    for (int off = 16; off; off >>= 1) s += __shfl_xor_sync(0xffffffffu, s, off);
    if ((tid & 31) == 0) red[tid >> 5] = s;
    __syncthreads();
    if (tid == 0) {
        float tot = 0.f;
        for (int i = 0; i < 8; ++i) tot += red[i];
        stat[0] = tot * (1.f / HH);
    }
    __syncthreads();
    float mu = stat[0];
    float v2 = 0.f;
    for (int i = tid; i < HH; i += 256) { float d = row[i] - mu; v2 += d * d; }
#pragma unroll
    for (int off = 16; off; off >>= 1) v2 += __shfl_xor_sync(0xffffffffu, v2, off);
    __syncthreads();
    if ((tid & 31) == 0) red[tid >> 5] = v2;
    __syncthreads();
    if (tid == 0) {
        float tot = 0.f;
        for (int i = 0; i < 8; ++i) tot += red[i];
        stat[1] = rsqrtf(tot * (1.f / HH) + 1e-5f);
    }
    __syncthreads();
    float inv = stat[1];
    for (int i = tid; i < HH; i += 256) {
        float v = (row[i] - mu) * inv * w[i] + bv[i];
        __nv_bfloat16 hi, lo;
        split_bf16(v, hi, lo);
        oh[orow + i] = hi;
        ol[orow + i] = lo;
    }
}

// ======================= launch =======================
extern "C" void kernel_launch(void* const* d_in, const int* in_sizes, int n_in,
                              void* d_out, int out_size)
{
    (void)in_sizes; (void)n_in; (void)out_size;
    const int*   ids = (const int*)d_in[0];
    const float* we  = (const float*)d_in[1];
    const float* pe  = (const float*)d_in[2];
    const float* Wih = (const float*)d_in[3];
    const float* Whh = (const float*)d_in[4];
    const float* bih = (const float*)d_in[5];
    const float* bhh = (const float*)d_in[6];
    const float* lnw = (const float*)d_in[7];
    const float* lnb = (const float*)d_in[8];
    float* out = (float*)d_out;

    __nv_bfloat16 *weh, *wel, *wihh, *wihl, *fh, *fl, *h0h, *h0l, *xnh, *xnl;
    float *gates, *h0, *h1; unsigned* counter;
    cudaGetSymbolAddress((void**)&weh,  g_weh);
    cudaGetSymbolAddress((void**)&wel,  g_wel);
    cudaGetSymbolAddress((void**)&wihh, g_wihh);
    cudaGetSymbolAddress((void**)&wihl, g_wihl);
    cudaGetSymbolAddress((void**)&fh,   g_fh);
    cudaGetSymbolAddress((void**)&fl,   g_fl);
    cudaGetSymbolAddress((void**)&h0h,  g_h0h);
    cudaGetSymbolAddress((void**)&h0l,  g_h0l);
    cudaGetSymbolAddress((void**)&xnh,  g_xnh);
    cudaGetSymbolAddress((void**)&xnl,  g_xnl);
    cudaGetSymbolAddress((void**)&gates, g_gates);
    cudaGetSymbolAddress((void**)&h0,    g_h0);
    cudaGetSymbolAddress((void**)&h1,    g_h1);
    cudaGetSymbolAddress((void**)&counter, g_counter);

    size_t lsmem = (size_t)(32 * 1028 + 4 * 1024 + 8 * 32 * 4 + 32 * 4 + 32) * sizeof(float);
    cudaFuncSetAttribute(lstm_layer_kernel,
                         cudaFuncAttributeMaxDynamicSharedMemorySize, (int)lsmem);
    cudaFuncSetAttribute(gemm_hmma_kernel,
                         cudaFuncAttributeMaxDynamicSharedMemorySize, GSMEM);

    // weight/input splits
    convsplit_kernel<<<(VV * HH / 4 + 255) / 256, 256>>>(we, weh, wel, VV * HH / 4);
    convsplit_kernel<<<(2 * 4 * HH * HH / 4 + 255) / 256, 256>>>(Wih, wihh, wihl,
                                                                 2 * 4 * HH * HH / 4);
    embed_kernel<<<dim3(TT, BB), 256>>>(ids, we, pe, fh, fl);

    // layer0 input gates
    gemm_hmma_kernel<<<dim3(4 * HH / 128, TT * BB / 128), 256, GSMEM>>>(
        fh, fl, wihh, wihl, bih, bhh, gates, 4 * HH);
    reset_counter_kernel<<<1, 32>>>(counter);
    lstm_layer_kernel<<<NBLK, 256, lsmem>>>(gates, Whh, h0, counter);

    // layer1
    convsplit_kernel<<<(TT * BB * HH / 4 + 255) / 256, 256>>>(h0, h0h, h0l, TT * BB * HH / 4);
    gemm_hmma_kernel<<<dim3(4 * HH / 128, TT * BB / 128), 256, GSMEM>>>(
        h0h, h0l, wihh + (size_t)4 * HH * HH, wihl + (size_t)4 * HH * HH,
        bih + 4 * HH, bhh + 4 * HH, gates, 4 * HH);
    reset_counter_kernel<<<1, 32>>>(counter);
    lstm_layer_kernel<<<NBLK, 256, lsmem>>>(gates, Whh + (size_t)4 * HH * HH, h1, counter);

    // layernorm + head
    layernorm_kernel<<<dim3(TT, BB), 256>>>(h1, lnw, lnb, xnh, xnl);
    gemm_hmma_kernel<<<dim3(VV / 128, TT * BB / 128), 256, GSMEM>>>(
        xnh, xnl, weh, wel, nullptr, nullptr, out, VV);
}

// round 9
// speedup vs baseline: 2.6322x; 1.0153x over previous
#include <cuda_runtime.h>
#include <cuda_bf16.h>
#include <cstdint>
#include <math.h>

#define TT 1024
#define BB 4
#define HH 1024
#define VV 32000
#define NBLK 128
#define UPB 8

typedef unsigned long long ull;

// ======================= helpers =======================
__device__ __forceinline__ uint32_t smem_to_u32(const void* p) {
    uint32_t a;
    asm("{ .reg .u64 t; cvta.to.shared.u64 t, %1; cvt.u32.u64 %0, t; }" : "=r"(a) : "l"(p));
    return a;
}
__device__ __forceinline__ void cp16(uint32_t dst, const void* src) {
    asm volatile("cp.async.cg.shared.global [%0], [%1], 16;" :: "r"(dst), "l"(src) : "memory");
}
#define CP_COMMIT() asm volatile("cp.async.commit_group;" ::: "memory")
#define CP_WAIT(n)  asm volatile("cp.async.wait_group %0;" :: "n"(n) : "memory")

#define LDSM_X4(r0, r1, r2, r3, addr) \
    asm volatile("ldmatrix.sync.aligned.m8n8.x4.shared.b16 {%0,%1,%2,%3}, [%4];" \
        : "=r"(r0), "=r"(r1), "=r"(r2), "=r"(r3) : "r"(addr))
#define MMA16816(c0, c1, c2, c3, a0, a1, a2, a3, b0, b1) \
    asm volatile("mma.sync.aligned.m16n8k16.row.col.f32.bf16.bf16.f32 " \
        "{%0,%1,%2,%3}, {%4,%5,%6,%7}, {%8,%9}, {%0,%1,%2,%3};" \
        : "+f"(c0), "+f"(c1), "+f"(c2), "+f"(c3) \
        : "r"(a0), "r"(a1), "r"(a2), "r"(a3), "r"(b0), "r"(b1))

// packed dual-fp32 FMA (FFMA2): acc.xy += w.xy * h.xy
#define FMA2(acc, w, h) \
    asm("fma.rn.f32x2 %0, %1, %2, %0;" : "+l"(acc) : "l"(w), "l"(h))
__device__ __forceinline__ float f2sum(ull v) {
    return __uint_as_float((unsigned)v) + __uint_as_float((unsigned)(v >> 32));
}

// ======================= scratch =======================
__device__ __nv_bfloat16 g_weh[(size_t)VV * HH];
__device__ __nv_bfloat16 g_wel[(size_t)VV * HH];
__device__ __nv_bfloat16 g_wihh[(size_t)2 * 4 * HH * HH];
__device__ __nv_bfloat16 g_wihl[(size_t)2 * 4 * HH * HH];
__device__ __nv_bfloat16 g_fh[(size_t)TT * BB * HH];
__device__ __nv_bfloat16 g_fl[(size_t)TT * BB * HH];
__device__ __nv_bfloat16 g_h0h[(size_t)TT * BB * HH];
__device__ __nv_bfloat16 g_h0l[(size_t)TT * BB * HH];
__device__ __nv_bfloat16 g_xnh[(size_t)TT * BB * HH];
__device__ __nv_bfloat16 g_xnl[(size_t)TT * BB * HH];
__device__ float g_gates[(size_t)TT * BB * 4 * HH];
__device__ float g_h0[(size_t)TT * BB * HH];
__device__ float g_h1[(size_t)TT * BB * HH];
__device__ unsigned g_counter;

__device__ __forceinline__ void split_bf16(float v, __nv_bfloat16& hi, __nv_bfloat16& lo) {
    __nv_bfloat16 h = __float2bfloat16(v);
    hi = h;
    lo = __float2bfloat16(v - __bfloat162float(h));
}

// ======================= fp32 -> bf16 hi/lo split =======================
__global__ __launch_bounds__(256) void convsplit_kernel(
    const float* __restrict__ in, __nv_bfloat16* __restrict__ hi,
    __nv_bfloat16* __restrict__ lo, int n4)
{
    int i = blockIdx.x * blockDim.x + threadIdx.x;
    if (i >= n4) return;
    float4 v = ((const float4*)in)[i];
    __nv_bfloat16 h0, h1, h2, h3, l0, l1, l2, l3;
    split_bf16(v.x, h0, l0); split_bf16(v.y, h1, l1);
    split_bf16(v.z, h2, l2); split_bf16(v.w, h3, l3);
    ((__nv_bfloat162*)hi)[i * 2 + 0] = __nv_bfloat162(h0, h1);
    ((__nv_bfloat162*)hi)[i * 2 + 1] = __nv_bfloat162(h2, h3);
    ((__nv_bfloat162*)lo)[i * 2 + 0] = __nv_bfloat162(l0, l1);
    ((__nv_bfloat162*)lo)[i * 2 + 1] = __nv_bfloat162(l2, l3);
}

// ======================= embedding -> bf16 split, time-major =======================
__global__ __launch_bounds__(256) void embed_kernel(
    const int* __restrict__ ids, const float* __restrict__ we,
    const float* __restrict__ pe, __nv_bfloat16* __restrict__ oh,
    __nv_bfloat16* __restrict__ ol)
{
    int t = blockIdx.x, b = blockIdx.y;
    int id = ids[b * TT + t];
    const float4* w = (const float4*)(we + (size_t)id * HH);
    const float4* p = (const float4*)(pe + (size_t)t * HH);
    size_t row = ((size_t)t * BB + b) * HH;
    for (int i = threadIdx.x; i < HH / 4; i += blockDim.x) {
        float4 a = w[i], c = p[i];
        float4 v = make_float4(a.x + c.x, a.y + c.y, a.z + c.z, a.w + c.w);
        __nv_bfloat16 h0, h1, h2, h3, l0, l1, l2, l3;
        split_bf16(v.x, h0, l0); split_bf16(v.y, h1, l1);
        split_bf16(v.z, h2, l2); split_bf16(v.w, h3, l3);
        ((__nv_bfloat162*)(oh + row))[i * 2 + 0] = __nv_bfloat162(h0, h1);
        ((__nv_bfloat162*)(oh + row))[i * 2 + 1] = __nv_bfloat162(h2, h3);
        ((__nv_bfloat162*)(ol + row))[i * 2 + 0] = __nv_bfloat162(l0, l1);
        ((__nv_bfloat162*)(ol + row))[i * 2 + 1] = __nv_bfloat162(l2, l3);
    }
}

// ======================= HMMA split-bf16 NT GEMM =======================
// NOW 2 CTAs/SM: __launch_bounds__(256,2) caps regs at 128; smem 2x40KB x 2 buf.
#define TSTRIDE 40
#define TILE_E  (128 * TSTRIDE)
#define TILE_BYTES (TILE_E * 2)            // 10240
#define BUF_BYTES (4 * TILE_BYTES)         // 40960
#define GSMEM (2 * BUF_BYTES)              // 81920

__global__ __launch_bounds__(256, 2) void gemm_hmma_kernel(
    const __nv_bfloat16* __restrict__ Ah, const __nv_bfloat16* __restrict__ Al,
    const __nv_bfloat16* __restrict__ Bh, const __nv_bfloat16* __restrict__ Bl,
    const float* __restrict__ bias0, const float* __restrict__ bias1,
    float* __restrict__ C, int N)
{
    extern __shared__ __nv_bfloat16 sm[];
    const uint32_t sbase = smem_to_u32(sm);
    const int tid = threadIdx.x;
    const int lane = tid & 31;
    const int wid = tid >> 5;
    const int wm = wid & 3;
    const int wn = wid >> 2;
    const int bn = blockIdx.x << 7;
    const int bm = blockIdx.y << 7;

    float acc[2][8][4];
#pragma unroll
    for (int mt = 0; mt < 2; ++mt)
#pragma unroll
        for (int nt = 0; nt < 8; ++nt)
#pragma unroll
            for (int q = 0; q < 4; ++q) acc[mt][nt][q] = 0.f;

    const __nv_bfloat16* srcs[4] = { Ah, Al, Bh, Bl };
    const int rb[4] = { bm, bm, bn, bn };

    auto load_chunk = [&](int c) {
        uint32_t buf = sbase + (c & 1) * BUF_BYTES;
#pragma unroll
        for (int tsel = 0; tsel < 4; ++tsel) {
            uint32_t dst = buf + tsel * TILE_BYTES;
            const __nv_bfloat16* base = srcs[tsel];
#pragma unroll
            for (int i = 0; i < 2; ++i) {
                int s = tid + (i << 8);
                int row = s >> 2, k8 = s & 3;
                cp16(dst + row * (TSTRIDE * 2) + k8 * 16,
                     base + (size_t)(rb[tsel] + row) * 1024 + c * 32 + k8 * 8);
            }
        }
        CP_COMMIT();
    };

    load_chunk(0);

    for (int c = 0; c < 32; ++c) {
        if (c < 31) { load_chunk(c + 1); CP_WAIT(1); }
        else        { CP_WAIT(0); }
        __syncthreads();

        uint32_t buf = sbase + (c & 1) * BUF_BYTES;
        const int a_r = (lane & 15);
        const int a_k = (lane >> 4) << 3;
        const int b_n = ((lane >> 4) << 3) + (lane & 7);
        const int b_k = ((lane >> 3) & 1) << 3;

#pragma unroll
        for (int ks = 0; ks < 2; ++ks) {
            const int kbase = ks << 4;
            uint32_t ah[2][4], al[2][4], bh[16], bl[16];
#pragma unroll
            for (int mt = 0; mt < 2; ++mt) {
                int row = wm * 32 + mt * 16 + a_r;
                uint32_t addr = buf + (row * TSTRIDE + kbase + a_k) * 2;
                LDSM_X4(ah[mt][0], ah[mt][1], ah[mt][2], ah[mt][3], addr);
                LDSM_X4(al[mt][0], al[mt][1], al[mt][2], al[mt][3], addr + TILE_BYTES);
            }
#pragma unroll
            for (int np = 0; np < 4; ++np) {
                int nrow = wn * 64 + np * 16 + b_n;
                uint32_t addr = buf + 2 * TILE_BYTES + (nrow * TSTRIDE + kbase + b_k) * 2;
                LDSM_X4(bh[np * 4 + 0], bh[np * 4 + 1], bh[np * 4 + 2], bh[np * 4 + 3], addr);
                LDSM_X4(bl[np * 4 + 0], bl[np * 4 + 1], bl[np * 4 + 2], bl[np * 4 + 3],
                        addr + TILE_BYTES);
            }
#pragma unroll
            for (int mt = 0; mt < 2; ++mt)
#pragma unroll
                for (int nt = 0; nt < 8; ++nt) {
                    float* cc = acc[mt][nt];
                    MMA16816(cc[0], cc[1], cc[2], cc[3],
                             ah[mt][0], ah[mt][1], ah[mt][2], ah[mt][3],
                             bh[nt * 2], bh[nt * 2 + 1]);
                    MMA16816(cc[0], cc[1], cc[2], cc[3],
                             al[mt][0], al[mt][1], al[mt][2], al[mt][3],
                             bh[nt * 2], bh[nt * 2 + 1]);
                    MMA16816(cc[0], cc[1], cc[2], cc[3],
                             ah[mt][0], ah[mt][1], ah[mt][2], ah[mt][3],
                             bl[nt * 2], bl[nt * 2 + 1]);
                }
        }
        __syncthreads();
    }

#pragma unroll
    for (int mt = 0; mt < 2; ++mt) {
        int row0 = bm + wm * 32 + mt * 16 + (lane >> 2);
#pragma unroll
        for (int nt = 0; nt < 8; ++nt) {
            int col = bn + wn * 64 + nt * 8 + ((lane & 3) << 1);
            float b0v = 0.f, b1v = 0.f;
            if (bias0) {
                b0v = bias0[col] + bias1[col];
                b1v = bias0[col + 1] + bias1[col + 1];
            }
            float* c0 = C + (size_t)row0 * N + col;
            float* c1 = C + (size_t)(row0 + 8) * N + col;
            *(float2*)c0 = make_float2(acc[mt][nt][0] + b0v, acc[mt][nt][1] + b1v);
            *(float2*)c1 = make_float2(acc[mt][nt][2] + b0v, acc[mt][nt][3] + b1v);
        }
    }
}

// ======================= persistent LSTM recurrence =======================
// R8 counter-barrier + NEW f32x2-packed dot products (halves FFMA issue count).
__device__ __forceinline__ float sigm(float x) { return 1.f / (1.f + expf(-x)); }

__global__ __launch_bounds__(256) void lstm_layer_kernel(
    const float* __restrict__ gates_in, const float* __restrict__ Whh,
    float* __restrict__ hout, unsigned* counter)
{
    extern __shared__ float smf[];
    float* Wsh  = smf;                      // [32][1028]  (row byte-stride 4112 = 16B-aligned)
    float* hsh  = Wsh + 32 * 1028;          // [4][1024]
    float* part = hsh + 4 * 1024;           // [8][32][4]
    float* gsm  = part + 8 * 32 * 4;        // [32][4]
    float* csh  = gsm + 32 * 4;             // [32]

    const int tid = threadIdx.x;
    const int blk = blockIdx.x;
    const int u0 = blk * UPB;

#pragma unroll
    for (int r = 0; r < 32; ++r) {
        int g = r >> 3, u = r & 7;
        const float* src = Whh + (size_t)(g * HH + u0 + u) * HH;
        *(float4*)(Wsh + r * 1028 + tid * 4) = *(const float4*)(src + tid * 4);
    }
    if (tid < 32) csh[tid] = 0.f;
    for (int i = tid * 4; i < BB * HH; i += 1024)
        *(float4*)(hsh + i) = make_float4(0.f, 0.f, 0.f, 0.f);
    __syncthreads();

    const int j  = tid & 31;
    const int ks = tid >> 5;
    const int jj = tid >> 2, bb = tid & 3;
    const int gg = jj >> 3, uu = jj & 7;
    const float* gptr = gates_in + (size_t)bb * (4 * HH) + gg * HH + u0 + uu;

    for (int t = 0; t < TT; ++t) {
        float gin = 0.f;
        if (tid < 128) gin = __ldg(gptr + (size_t)t * BB * 4 * HH);

        if (t > 0) {
            if (tid == 0) {
                unsigned tgt = (unsigned)NBLK * (unsigned)t;
                unsigned v;
                do {
                    asm volatile("ld.acquire.gpu.global.u32 %0, [%1];"
                                 : "=r"(v) : "l"(counter));
                } while (v < tgt);
            }
            __syncthreads();
            const float* hp = hout + (size_t)(t - 1) * BB * HH;
            for (int i = tid * 4; i < BB * HH; i += 1024)
                *(float4*)(hsh + i) = __ldcg((const float4*)(hp + i));
            __syncthreads();
        }

        // packed f32x2 partial dots: acc.xy[b] += W[j][k,k+1] * h[b][k,k+1]
        {
            const float* wr = Wsh + j * 1028 + (ks << 7);
            const float* hb = hsh + (ks << 7);
            ull a0 = 0ull, a1 = 0ull, a2 = 0ull, a3 = 0ull;
#pragma unroll 8
            for (int k = 0; k < 128; k += 4) {
                ulonglong2 wv = *(const ulonglong2*)(wr + k);
                ulonglong2 x0 = *(const ulonglong2*)(hb + k);
                ulonglong2 x1 = *(const ulonglong2*)(hb + 1024 + k);
                ulonglong2 x2 = *(const ulonglong2*)(hb + 2048 + k);
                ulonglong2 x3 = *(const ulonglong2*)(hb + 3072 + k);
                FMA2(a0, wv.x, x0.x); FMA2(a0, wv.y, x0.y);
                FMA2(a1, wv.x, x1.x); FMA2(a1, wv.y, x1.y);
                FMA2(a2, wv.x, x2.x); FMA2(a2, wv.y, x2.y);
                FMA2(a3, wv.x, x3.x); FMA2(a3, wv.y, x3.y);
            }
            *(float4*)(part + ((ks << 5) + j) * 4) =
                make_float4(f2sum(a0), f2sum(a1), f2sum(a2), f2sum(a3));
        }
        __syncthreads();

        if (tid < 128) {
            float s = gin;
#pragma unroll
            for (int q = 0; q < 8; ++q) s += part[((q << 5) + jj) * 4 + bb];
            gsm[jj * 4 + bb] = s;
        }
        __syncthreads();

        if (tid < 32) {
            int u = tid >> 2, b = tid & 3;
            float gi = gsm[(0 * 8 + u) * 4 + b];
            float gf = gsm[(1 * 8 + u) * 4 + b];
            float gc = gsm[(2 * 8 + u) * 4 + b];
            float go = gsm[(3 * 8 + u) * 4 + b];
            float cc = csh[tid];
            float cn = sigm(gf) * cc + sigm(gi) * tanhf(gc);
            float hn = sigm(go) * tanhf(cn);
            csh[tid] = cn;
            hout[((size_t)t * BB + b) * HH + u0 + u] = hn;
        }
        __syncthreads();
        if (tid == 0) {
            asm volatile("red.release.gpu.global.add.u32 [%0], %1;"
                         :: "l"(counter), "r"(1u) : "memory");
        }
    }
}

__global__ void reset_counter_kernel(unsigned* c)
{
    if (threadIdx.x == 0) *c = 0u;
}

// ======================= LayerNorm -> bf16 split, batch-major =======================
__global__ __launch_bounds__(256) void layernorm_kernel(
    const float* __restrict__ in, const float* __restrict__ w,
    const float* __restrict__ bv, __nv_bfloat16* __restrict__ oh,
    __nv_bfloat16* __restrict__ ol)
{
    int t = blockIdx.x, b = blockIdx.y;
    const float* x = in + ((size_t)t * BB + b) * HH;
    size_t orow = ((size_t)b * TT + t) * HH;
    __shared__ float row[HH];
    __shared__ float red[8];
    __shared__ float stat[2];
    int tid = threadIdx.x;

    float s = 0.f;
    for (int i = tid; i < HH; i += 256) { float v = x[i]; row[i] = v; s += v; }
#pragma unroll
    for (int off = 16; off; off >>= 1) s += __shfl_xor_sync(0xffffffffu, s, off);
    if ((tid & 31) == 0) red[tid >> 5] = s;
    __syncthreads();
    if (tid == 0) {
        float tot = 0.f;
        for (int i = 0; i < 8; ++i) tot += red[i];
        stat[0] = tot * (1.f / HH);
    }
    __syncthreads();
    float mu = stat[0];
    float v2 = 0.f;
    for (int i = tid; i < HH; i += 256) { float d = row[i] - mu; v2 += d * d; }
#pragma unroll
    for (int off = 16; off; off >>= 1) v2 += __shfl_xor_sync(0xffffffffu, v2, off);
    __syncthreads();
    if ((tid & 31) == 0) red[tid >> 5] = v2;
    __syncthreads();
    if (tid == 0) {
        float tot = 0.f;
        for (int i = 0; i < 8; ++i) tot += red[i];
        stat[1] = rsqrtf(tot * (1.f / HH) + 1e-5f);
    }
    __syncthreads();
    float inv = stat[1];
    for (int i = tid; i < HH; i += 256) {
        float v = (row[i] - mu) * inv * w[i] + bv[i];
        __nv_bfloat16 hi, lo;
        split_bf16(v, hi, lo);
        oh[orow + i] = hi;
        ol[orow + i] = lo;
    }
}

// ======================= launch =======================
extern "C" void kernel_launch(void* const* d_in, const int* in_sizes, int n_in,
                              void* d_out, int out_size)
{
    (void)in_sizes; (void)n_in; (void)out_size;
    const int*   ids = (const int*)d_in[0];
    const float* we  = (const float*)d_in[1];
    const float* pe  = (const float*)d_in[2];
    const float* Wih = (const float*)d_in[3];
    const float* Whh = (const float*)d_in[4];
    const float* bih = (const float*)d_in[5];
    const float* bhh = (const float*)d_in[6];
    const float* lnw = (const float*)d_in[7];
    const float* lnb = (const float*)d_in[8];
    float* out = (float*)d_out;

    __nv_bfloat16 *weh, *wel, *wihh, *wihl, *fh, *fl, *h0h, *h0l, *xnh, *xnl;
    float *gates, *h0, *h1; unsigned* counter;
    cudaGetSymbolAddress((void**)&weh,  g_weh);
    cudaGetSymbolAddress((void**)&wel,  g_wel);
    cudaGetSymbolAddress((void**)&wihh, g_wihh);
    cudaGetSymbolAddress((void**)&wihl, g_wihl);
    cudaGetSymbolAddress((void**)&fh,   g_fh);
    cudaGetSymbolAddress((void**)&fl,   g_fl);
    cudaGetSymbolAddress((void**)&h0h,  g_h0h);
    cudaGetSymbolAddress((void**)&h0l,  g_h0l);
    cudaGetSymbolAddress((void**)&xnh,  g_xnh);
    cudaGetSymbolAddress((void**)&xnl,  g_xnl);
    cudaGetSymbolAddress((void**)&gates, g_gates);
    cudaGetSymbolAddress((void**)&h0,    g_h0);
    cudaGetSymbolAddress((void**)&h1,    g_h1);
    cudaGetSymbolAddress((void**)&counter, g_counter);

    size_t lsmem = (size_t)(32 * 1028 + 4 * 1024 + 8 * 32 * 4 + 32 * 4 + 32) * sizeof(float);
    cudaFuncSetAttribute(lstm_layer_kernel,
                         cudaFuncAttributeMaxDynamicSharedMemorySize, (int)lsmem);
    cudaFuncSetAttribute(gemm_hmma_kernel,
                         cudaFuncAttributeMaxDynamicSharedMemorySize, GSMEM);

    // weight/input splits
    convsplit_kernel<<<(VV * HH / 4 + 255) / 256, 256>>>(we, weh, wel, VV * HH / 4);
    convsplit_kernel<<<(2 * 4 * HH * HH / 4 + 255) / 256, 256>>>(Wih, wihh, wihl,
                                                                 2 * 4 * HH * HH / 4);
    embed_kernel<<<dim3(TT, BB), 256>>>(ids, we, pe, fh, fl);

    // layer0 input gates
    gemm_hmma_kernel<<<dim3(4 * HH / 128, TT * BB / 128), 256, GSMEM>>>(
        fh, fl, wihh, wihl, bih, bhh, gates, 4 * HH);
    reset_counter_kernel<<<1, 32>>>(counter);
    lstm_layer_kernel<<<NBLK, 256, lsmem>>>(gates, Whh, h0, counter);

    // layer1
    convsplit_kernel<<<(TT * BB * HH / 4 + 255) / 256, 256>>>(h0, h0h, h0l, TT * BB * HH / 4);
    gemm_hmma_kernel<<<dim3(4 * HH / 128, TT * BB / 128), 256, GSMEM>>>(
        h0h, h0l, wihh + (size_t)4 * HH * HH, wihl + (size_t)4 * HH * HH,
        bih + 4 * HH, bhh + 4 * HH, gates, 4 * HH);
    reset_counter_kernel<<<1, 32>>>(counter);
    lstm_layer_kernel<<<NBLK, 256, lsmem>>>(gates, Whh + (size_t)4 * HH * HH, h1, counter);

    // layernorm + head
    layernorm_kernel<<<dim3(TT, BB), 256>>>(h1, lnw, lnb, xnh, xnl);
    gemm_hmma_kernel<<<dim3(VV / 128, TT * BB / 128), 256, GSMEM>>>(
        xnh, xnl, weh, wel, nullptr, nullptr, out, VV);
}